// round 3
// baseline (speedup 1.0000x reference)
#include <cuda_runtime.h>

// Motion loss: loss_rot + loss_fk + loss_pos, fused single pass.
// B=64, T=2048, J=24, C=4*J+3=99.
//
// Thread = one (b,t) pair. Loads of Y_m/X_m are coalesced across t (innermost dim).
// FK chain kept entirely in registers via a 3-slot transform/result pool derived
// from topology liveness analysis. Deterministic 2-stage reduction.

#define NB 64
#define NT 2048
#define NJ 24
#define NC 99

#define TPB 128                    // threads per block (t-chunk)
#define GX  (NT / TPB)             // 16
#define NBLK (GX * NB)             // 1024 partial sums

__device__ float g_partial[NBLK];

// Slot assignment (A=0,B=1,C=2) from liveness analysis of the chain.
// PSLOT[j] = pool slot holding transform/result of parent(j)  (-1 for root)
// MSLOT[j] = pool slot to store joint j's transform/result into (-1 if leaf)
#define PSLOT_INIT {-1,0,0,0,1,2,0,1,2,0,1,2,0,0,0,1,2,0,2,0,2,0,2,0}
#define MSLOT_INIT { 0,1,2,0,1,2,0,1,2,0,-1,-1,1,2,0,-1,2,0,2,0,2,0,-1,-1}

__device__ __forceinline__ void quat2mat(float w, float x, float y, float z, float* m)
{
    float s = __fdividef(2.0f, w*w + x*x + y*y + z*z);
    float xx = x*x, yy = y*y, zz = z*z;
    float xy = x*y, xz = x*z, yz = y*z;
    float wx = w*x, wy = w*y, wz = w*z;
    m[0] = 1.0f - s*(yy + zz); m[1] = s*(xy - wz);        m[2] = s*(xz + wy);
    m[3] = s*(xy + wz);        m[4] = 1.0f - s*(xx + zz); m[5] = s*(yz - wx);
    m[6] = s*(xz - wy);        m[7] = s*(yz + wx);        m[8] = 1.0f - s*(xx + yy);
}

__device__ __forceinline__ void mm33(const float* a, const float* b, float* c)
{
#pragma unroll
    for (int i = 0; i < 3; ++i)
#pragma unroll
        for (int j = 0; j < 3; ++j)
            c[i*3 + j] = a[i*3 + 0]*b[0*3 + j] + a[i*3 + 1]*b[1*3 + j] + a[i*3 + 2]*b[2*3 + j];
}

__device__ __forceinline__ void mv3(const float* a, const float* v, float* r)
{
#pragma unroll
    for (int i = 0; i < 3; ++i)
        r[i] = a[i*3 + 0]*v[0] + a[i*3 + 1]*v[1] + a[i*3 + 2]*v[2];
}

__global__ __launch_bounds__(TPB)
void motion_loss_kernel(const float* __restrict__ Ym, const float* __restrict__ Xm,
                        const float* __restrict__ Yt, const float* __restrict__ Xt,
                        const float* __restrict__ jw)
{
    const int b   = blockIdx.y;
    const int tid = threadIdx.x;
    const int t   = blockIdx.x * TPB + tid;

    __shared__ float offY[NJ][3];
    __shared__ float offX[NJ][3];
    __shared__ float ws[NJ];

    if (tid < NJ * 3) {
        offY[tid / 3][tid % 3] = Yt[b * NJ * 3 + tid];
        offX[tid / 3][tid % 3] = Xt[b * NJ * 3 + tid];
    }
    if (tid < NJ) ws[tid] = jw[tid];
    __syncthreads();

    const float* ymb = Ym + (size_t)b * NC * NT + t;
    const float* xmb = Xm + (size_t)b * NC * NT + t;

    float accRot = 0.0f, accFk = 0.0f, accPos = 0.0f;

    // 3-slot register pools (per motion): transforms + world positions
    float Ty[3][9], Tx[3][9];
    float Ry[3][3], Rx[3][3];

    const int PSLOT[NJ] = PSLOT_INIT;
    const int MSLOT[NJ] = MSLOT_INIT;

#pragma unroll
    for (int j = 0; j < NJ; ++j) {
        const int ps = PSLOT[j];
        const int ms = MSLOT[j];

        float qy[4], qx[4];
#pragma unroll
        for (int k = 0; k < 4; ++k) {
            qy[k] = __ldcs(&ymb[(size_t)(4*j + k) * NT]);
            qx[k] = __ldcs(&xmb[(size_t)(4*j + k) * NT]);
        }

        accRot += ws[j] * (fabsf(qy[0]-qx[0]) + fabsf(qy[1]-qx[1]) +
                           fabsf(qy[2]-qx[2]) + fabsf(qy[3]-qx[3]));

        float Ra[9], Rb[9];
        quat2mat(qy[0], qy[1], qy[2], qy[3], Ra);
        quat2mat(qx[0], qx[1], qx[2], qx[3], Rb);

        float Tyc[9], Txc[9];
        if (ps >= 0) {
            mm33(Ty[ps], Ra, Tyc);
            mm33(Tx[ps], Rb, Txc);
        } else {
#pragma unroll
            for (int k = 0; k < 9; ++k) { Tyc[k] = Ra[k]; Txc[k] = Rb[k]; }
        }

        float ry[3], rx[3];
        mv3(Tyc, &offY[j][0], ry);
        mv3(Txc, &offX[j][0], rx);
        if (ps >= 0) {
#pragma unroll
            for (int k = 0; k < 3; ++k) { ry[k] += Ry[ps][k]; rx[k] += Rx[ps][k]; }
        }

        accFk += ws[j] * (fabsf(ry[0]-rx[0]) + fabsf(ry[1]-rx[1]) + fabsf(ry[2]-rx[2]));

        if (ms >= 0) {
#pragma unroll
            for (int k = 0; k < 9; ++k) { Ty[ms][k] = Tyc[k]; Tx[ms][k] = Txc[k]; }
#pragma unroll
            for (int k = 0; k < 3; ++k) { Ry[ms][k] = ry[k];  Rx[ms][k] = rx[k]; }
        }
    }

    // position loss: channels 96..98
#pragma unroll
    for (int k = 0; k < 3; ++k)
        accPos += fabsf(__ldcs(&ymb[(size_t)(NC - 3 + k) * NT]) -
                        __ldcs(&xmb[(size_t)(NC - 3 + k) * NT]));

    const float cRot = 1.0f / ((float)NB * NT * NJ * 4);
    const float cFk  = 1.0f / ((float)NB * NT * NJ * 3);
    const float cPos = 1.0f / ((float)NB * NT * 3);
    float total = accRot * cRot + accFk * cFk + accPos * cPos;

    // deterministic block reduction: warp shuffle, then cross-warp via smem
#pragma unroll
    for (int off = 16; off > 0; off >>= 1)
        total += __shfl_down_sync(0xffffffffu, total, off);

    __shared__ float wsum[TPB / 32];
    if ((tid & 31) == 0) wsum[tid >> 5] = total;
    __syncthreads();
    if (tid == 0) {
        float s = 0.0f;
#pragma unroll
        for (int wgi = 0; wgi < TPB / 32; ++wgi) s += wsum[wgi];
        g_partial[blockIdx.y * gridDim.x + blockIdx.x] = s;
    }
}

__global__ __launch_bounds__(NBLK)
void reduce_final_kernel(float* __restrict__ out)
{
    __shared__ float s[NBLK];
    const int tid = threadIdx.x;
    s[tid] = g_partial[tid];
    __syncthreads();
#pragma unroll
    for (int st = NBLK / 2; st > 0; st >>= 1) {
        if (tid < st) s[tid] += s[tid + st];
        __syncthreads();
    }
    if (tid == 0) out[0] = s[0];
}

extern "C" void kernel_launch(void* const* d_in, const int* in_sizes, int n_in,
                              void* d_out, int out_size)
{
    const float* Ym = (const float*)d_in[0];
    const float* Xm = (const float*)d_in[1];
    const float* Yt = (const float*)d_in[2];
    const float* Xt = (const float*)d_in[3];
    const float* jw = (const float*)d_in[4];

    dim3 grid(GX, NB);
    motion_loss_kernel<<<grid, TPB>>>(Ym, Xm, Yt, Xt, jw);
    reduce_final_kernel<<<1, NBLK>>>((float*)d_out);
}